// round 15
// baseline (speedup 1.0000x reference)
#include <cuda_runtime.h>
#include <cuda_bf16.h>
#include <math.h>
#include <stdint.h>

#define BB 4
#define TT 2048
#define CC 1024
#define HH 64
#define NROWS (BB * TT)   // 8192

// x fragments for proj GEMM
__device__ uint32_t g_afrag[512 * 64 * 2 * 128];
__device__ uint32_t g_bfrag[64 * 24 * 2 * 64];
// q/k/v in mma fragment form, produced by gemm epilogue
__device__ uint32_t g_qf[4 * 128 * 4 * 2 * 128];   // [b][mtile][ks][prec][lane*4+r]
__device__ uint32_t g_kf[4 * 256 * 4 * 2 * 64];    // [b][keyblk][ks][prec][lane*2+r]
__device__ uint32_t g_vf[4 * 128 * 8 * 2 * 64];    // [b][keytile][nt][prec][lane*2+r]

typedef unsigned long long ull;
union U64 { ull u; uint32_t s[2]; };

// ---------------- helpers ----------------
__device__ __forceinline__ ull lds_u64(const void* p) {
    uint32_t sa = (uint32_t)__cvta_generic_to_shared(p);
    ull r;
    asm volatile("ld.shared.u64 %0, [%1];" : "=l"(r) : "r"(sa));
    return r;
}
__device__ __forceinline__ void cp_async16(void* smem_dst, const void* gptr) {
    uint32_t sa = (uint32_t)__cvta_generic_to_shared(smem_dst);
    asm volatile("cp.async.cg.shared.global [%0], [%1], 16;" :: "r"(sa), "l"(gptr));
}
#define CP_COMMIT() asm volatile("cp.async.commit_group;")
#define CP_WAIT(n)  asm volatile("cp.async.wait_group %0;" :: "n"(n))
#define PBAR(g)     asm volatile("bar.sync %0, 64;" :: "r"((g) + 1) : "memory")

__device__ __forceinline__ uint32_t pack_bf16x2(float a, float b) {
    __nv_bfloat162 t;
    t.x = __float2bfloat16_rn(a);
    t.y = __float2bfloat16_rn(b);
    return *(uint32_t*)&t;
}
__device__ __forceinline__ void split2(float a, float b, uint32_t& hi, uint32_t& lo) {
    __nv_bfloat16 ha = __float2bfloat16_rn(a);
    __nv_bfloat16 hb = __float2bfloat16_rn(b);
    __nv_bfloat162 th; th.x = ha; th.y = hb;
    hi = *(uint32_t*)&th;
    lo = pack_bf16x2(a - __bfloat162float(ha), b - __bfloat162float(hb));
}
__device__ __forceinline__ void mma_bf16(float* c, const uint32_t* a, const uint32_t* b) {
    asm volatile(
        "mma.sync.aligned.m16n8k16.row.col.f32.bf16.bf16.f32 "
        "{%0,%1,%2,%3}, {%4,%5,%6,%7}, {%8,%9}, {%0,%1,%2,%3};"
        : "+f"(c[0]), "+f"(c[1]), "+f"(c[2]), "+f"(c[3])
        : "r"(a[0]), "r"(a[1]), "r"(a[2]), "r"(a[3]), "r"(b[0]), "r"(b[1]));
}

// ---------------------------------------------------------------------------
// Kernel 0a: x -> bf16 (hi,lo) A-fragments.
// ---------------------------------------------------------------------------
__global__ __launch_bounds__(256) void split_a_kernel(const float* __restrict__ x)
{
    const int unit = blockIdx.x * 8 + (threadIdx.x >> 5);
    const int lane = threadIdx.x & 31;
    const int mt   = unit >> 6;
    const int ks   = unit & 63;
    const uint32_t base = (uint32_t)(mt * 64 + ks) * 256;

#pragma unroll
    for (int r = 0; r < 4; r++) {
        const int m = mt * 16 + (lane >> 2) + ((r & 1) << 3);
        const int k = ks * 16 + ((lane & 3) << 1) + ((r >> 1) << 3);
        const float2 v = *(const float2*)&x[(size_t)m * CC + k];
        uint32_t hi, lo;
        split2(v.x, v.y, hi, lo);
        g_afrag[base + lane * 4 + r]       = hi;
        g_afrag[base + 128 + lane * 4 + r] = lo;
    }
}

// ---------------------------------------------------------------------------
// Kernel 0b: W -> bf16 (hi,lo) B-fragments.
// ---------------------------------------------------------------------------
__global__ __launch_bounds__(256) void split_b_kernel(
    const float* __restrict__ Wq,
    const float* __restrict__ Wk,
    const float* __restrict__ Wv)
{
    const int idx  = blockIdx.x * 256 + threadIdx.x;
    const int lane = idx & 31;
    const int nt   = (idx >> 5) % 24;
    const int ks   = idx / 768;
    const int n    = nt * 8 + (lane >> 2);
    const float* W = (n < 64) ? Wq : (n < 128) ? Wk : Wv;
    const int nc   = n & 63;
    const uint32_t base = (uint32_t)(ks * 24 + nt) * 128;

#pragma unroll
    for (int r = 0; r < 2; r++) {
        const int k = ks * 16 + ((lane & 3) << 1) + (r << 3);
        const float v0 = W[k * HH + nc];
        const float v1 = W[(k + 1) * HH + nc];
        uint32_t hi, lo;
        split2(v0, v1, hi, lo);
        g_bfrag[base + lane * 2 + r]      = hi;
        g_bfrag[base + 64 + lane * 2 + r] = lo;
    }
}

// ---------------------------------------------------------------------------
// Kernel 1: QKV projection via mma.sync, 256 threads / 8 warps.
// Warp = (mtile = w&3, nhalf = w>>2); 12 n-tiles x 3 mma per warp per k-step.
// Epilogue: nhalf0 -> Q + K(ks 0,1); nhalf1 -> K(ks 2,3) + V.
// ---------------------------------------------------------------------------
__global__ __launch_bounds__(256) void gemm_kernel()
{
    __shared__ uint32_t As[2][4 * 256];    // 8 KB
    __shared__ uint32_t Bs[2][24 * 128];   // 24 KB
    __shared__ float    Vsm[4][16][64];    // 16 KB

    const int tid   = threadIdx.x;
    const int w     = tid >> 5;
    const int lane  = tid & 31;
    const int mtile = w & 3;
    const int nhalf = w >> 2;
    const int ntb   = nhalf * 12;
    const int mt0   = blockIdx.x * 4;
    const int row0  = blockIdx.x * 64;

    float acc[12][4];
#pragma unroll
    for (int nt = 0; nt < 12; nt++)
#pragma unroll
        for (int e = 0; e < 4; e++) acc[nt][e] = 0.f;

    // prologue: kstep 0 -> buf 0
    {
        const int chunk = tid >> 6;
        const int within = (tid & 63) * 4;
        cp_async16(&As[0][chunk * 256 + within],
                   g_afrag + (uint32_t)((mt0 + chunk) * 64 + 0) * 256 + within);
#pragma unroll
        for (int i = 0; i < 3; i++) {
            const int u = tid + i * 256;
            cp_async16(&Bs[0][u * 4], g_bfrag + u * 4);
        }
        CP_COMMIT();
    }

    for (int ks = 0; ks < 64; ks++) {
        const int buf = ks & 1;
        CP_WAIT(0);
        __syncthreads();

        if (ks + 1 < 64) {
            const int chunk = tid >> 6;
            const int within = (tid & 63) * 4;
            cp_async16(&As[buf ^ 1][chunk * 256 + within],
                       g_afrag + (uint32_t)((mt0 + chunk) * 64 + ks + 1) * 256 + within);
#pragma unroll
            for (int i = 0; i < 3; i++) {
                const int u = tid + i * 256;
                cp_async16(&Bs[buf ^ 1][u * 4],
                           g_bfrag + (uint32_t)(ks + 1) * 3072 + u * 4);
            }
            CP_COMMIT();
        }

        uint32_t ah[4], al[4];
        *(uint4*)ah = *(const uint4*)&As[buf][mtile * 256 + lane * 4];
        *(uint4*)al = *(const uint4*)&As[buf][mtile * 256 + 128 + lane * 4];

#pragma unroll
        for (int nt = 0; nt < 12; nt++) {
            const int ntg = ntb + nt;
            uint32_t bh[2], bl[2];
            *(uint2*)bh = *(const uint2*)&Bs[buf][ntg * 128 + lane * 2];
            *(uint2*)bl = *(const uint2*)&Bs[buf][ntg * 128 + 64 + lane * 2];
            mma_bf16(acc[nt], ah, bh);
            mma_bf16(acc[nt], ah, bl);
            mma_bf16(acc[nt], al, bh);
        }
    }

    // ---- epilogue: write fragment-form q/k/v ----
    const int rw  = row0 + mtile * 16;
    const int bb  = rw >> 11;
    const int mtb = (rw & 2047) >> 4;
    const int kb0 = (rw & 2047) >> 3;
    const int ktb = mtb;
    const int qlr = lane >> 2;
    const int qlc = lane & 3;

    if (nhalf == 0) {
        // Q: A-fragments from acc[0..7]
#pragma unroll
        for (int ks = 0; ks < 4; ks++) {
            uint32_t h0, l0, h1, l1, h2, l2, h3, l3;
            split2(acc[2 * ks][0],     acc[2 * ks][1],     h0, l0);
            split2(acc[2 * ks][2],     acc[2 * ks][3],     h1, l1);
            split2(acc[2 * ks + 1][0], acc[2 * ks + 1][1], h2, l2);
            split2(acc[2 * ks + 1][2], acc[2 * ks + 1][3], h3, l3);
            const uint32_t base = (uint32_t)(((bb * 128 + mtb) * 4 + ks) * 2) * 128 + lane * 4;
            *(uint4*)&g_qf[base]       = make_uint4(h0, h1, h2, h3);
            *(uint4*)&g_qf[base + 128] = make_uint4(l0, l1, l2, l3);
        }
        // K: ks 0,1 from acc[8..11]
#pragma unroll
        for (int ks = 0; ks < 2; ks++) {
            const float* aE = acc[8 + 2 * ks];
            const float* aO = acc[9 + 2 * ks];
            uint32_t b0h, b0l, b1h, b1l;
            split2(aE[0], aE[1], b0h, b0l);
            split2(aO[0], aO[1], b1h, b1l);
            uint32_t base = (uint32_t)(((bb * 256 + kb0) * 4 + ks) * 2) * 64 + lane * 2;
            *(uint2*)&g_kf[base]      = make_uint2(b0h, b1h);
            *(uint2*)&g_kf[base + 64] = make_uint2(b0l, b1l);
            split2(aE[2], aE[3], b0h, b0l);
            split2(aO[2], aO[3], b1h, b1l);
            base = (uint32_t)(((bb * 256 + kb0 + 1) * 4 + ks) * 2) * 64 + lane * 2;
            *(uint2*)&g_kf[base]      = make_uint2(b0h, b1h);
            *(uint2*)&g_kf[base + 64] = make_uint2(b0l, b1l);
        }
    } else {
        // K: ks 2,3 from acc[0..3]
#pragma unroll
        for (int ks = 2; ks < 4; ks++) {
            const float* aE = acc[2 * ks - 4];
            const float* aO = acc[2 * ks - 3];
            uint32_t b0h, b0l, b1h, b1l;
            split2(aE[0], aE[1], b0h, b0l);
            split2(aO[0], aO[1], b1h, b1l);
            uint32_t base = (uint32_t)(((bb * 256 + kb0) * 4 + ks) * 2) * 64 + lane * 2;
            *(uint2*)&g_kf[base]      = make_uint2(b0h, b1h);
            *(uint2*)&g_kf[base + 64] = make_uint2(b0l, b1l);
            split2(aE[2], aE[3], b0h, b0l);
            split2(aO[2], aO[3], b1h, b1l);
            base = (uint32_t)(((bb * 256 + kb0 + 1) * 4 + ks) * 2) * 64 + lane * 2;
            *(uint2*)&g_kf[base]      = make_uint2(b0h, b1h);
            *(uint2*)&g_kf[base + 64] = make_uint2(b0l, b1l);
        }
        // V: stage f32 to smem, then transposed B-fragments (acc[4..11])
#pragma unroll
        for (int dt = 0; dt < 8; dt++) {
            const int d0 = dt * 8 + qlc * 2;
            Vsm[mtile][qlr][d0]         = acc[4 + dt][0];
            Vsm[mtile][qlr][d0 + 1]     = acc[4 + dt][1];
            Vsm[mtile][qlr + 8][d0]     = acc[4 + dt][2];
            Vsm[mtile][qlr + 8][d0 + 1] = acc[4 + dt][3];
        }
        __syncwarp();
#pragma unroll
        for (int nt = 0; nt < 8; nt++) {
#pragma unroll
            for (int r = 0; r < 2; r++) {
                const int kl_ = qlc * 2 + r * 8;
                const int dd  = nt * 8 + qlr;
                uint32_t h, lo;
                split2(Vsm[mtile][kl_][dd], Vsm[mtile][kl_ + 1][dd], h, lo);
                const uint32_t base = (uint32_t)(((bb * 128 + ktb) * 8 + nt) * 2) * 64 + lane * 2 + r;
                g_vf[base]      = h;
                g_vf[base + 64] = lo;
            }
        }
    }
}

// ---------------------------------------------------------------------------
// Kernel 2: causal attention, all-HMMA, 4-way key split across 8 warps.
// 128 blocks (32 pairs x 4 batches) x 256 threads. Phases qt = p, 63-p.
// Warp w: m16 tile (w&1), key group g (w>>1, 0..3); 32-key tiles, t = g,
// g+4, ... Each group: K/V double buffers + named barrier. Phase-end 4-way
// split-KV merge via smem staging.
// ---------------------------------------------------------------------------
#define KBUF(g, buf) (((g) * 2 + (buf)) * 2048)
#define VBUF(g, buf) (16384 + ((g) * 2 + (buf)) * 2048)
#define AQF 32768
#define ATTN_SMEM_BYTES (34816 * 4)    // 139264 B = 136 KB

__global__ __launch_bounds__(256) void attn_kernel(float* __restrict__ out)
{
    extern __shared__ uint32_t smu[];

    const int b    = blockIdx.y;
    const int p    = blockIdx.x;         // 0..31
    const int tid  = threadIdx.x;
    const int w    = tid >> 5;
    const int l    = tid & 31;
    const int tile = w & 1;              // m16 tile within the 32-row q-tile
    const int g    = w >> 1;             // key group (0..3)
    const int lt   = tid & 63;           // thread index within group
    const int qlr  = l >> 2;
    const int qlc  = l & 3;

    const uint32_t* qfb = g_qf + (size_t)b * 131072;
    const uint32_t* kfb = g_kf + (size_t)b * 131072;
    const uint32_t* vfb = g_vf + (size_t)b * 131072;
    float* ob = out + (size_t)b * TT * HH;

    for (int phase = 0; phase < 2; phase++) {
        const int qt = phase ? (63 - p) : p;
        const int qs = qt * 32;
        __syncthreads();    // previous phase fully done with smem (incl. merge)

        const int nkb = (qs + 63) >> 5;   // 32-key tiles = qt + 1

        // Q fragments (8 KB, all threads)
        {
            const uint32_t* src = qfb + (uint32_t)(qt * 2) * 1024;
#pragma unroll
            for (int i = 0; i < 2; i++) {
                const int u = tid + i * 256;
                cp_async16(&smu[AQF + u * 4], src + u * 4);
            }
        }
        // group's first key tile (t = g), if any
        if (g < nkb) {
            const uint32_t* ks_ = kfb + (uint32_t)g * 2048;
            const uint32_t* vs_ = vfb + (uint32_t)g * 2048;
#pragma unroll
            for (int i = 0; i < 8; i++) {
                const int u = lt + i * 64;
                cp_async16(&smu[KBUF(g, 0) + u * 4], ks_ + u * 4);
                cp_async16(&smu[VBUF(g, 0) + u * 4], vs_ + u * 4);
            }
        }
        CP_COMMIT();
        CP_WAIT(0);
        __syncthreads();

        float oacc[8][4];
#pragma unroll
        for (int nt = 0; nt < 8; nt++)
#pragma unroll
            for (int e = 0; e < 4; e++) oacc[nt][e] = 0.f;
        float m0 = -INFINITY, m1 = -INFINITY, ls0 = 0.f, ls1 = 0.f;
        const int r0 = qs + tile * 16 + qlr;
        const int r1 = r0 + 8;

        for (int t = g; t < nkb; t += 4) {
            const int buf = (t >> 2) & 1;
            if (t + 4 < nkb) {
                const uint32_t* ks_ = kfb + (uint32_t)(t + 4) * 2048;
                const uint32_t* vs_ = vfb + (uint32_t)(t + 4) * 2048;
#pragma unroll
                for (int i = 0; i < 8; i++) {
                    const int u = lt + i * 64;
                    cp_async16(&smu[KBUF(g, buf ^ 1) + u * 4], ks_ + u * 4);
                    cp_async16(&smu[VBUF(g, buf ^ 1) + u * 4], vs_ + u * 4);
                }
                CP_COMMIT();
            }

            // ---- scores: 3-product split bf16 HMMA (4 key blocks of 8) ----
            float sacc[4][4];
#pragma unroll
            for (int kb = 0; kb < 4; kb++)
#pragma unroll
                for (int e = 0; e < 4; e++) sacc[kb][e] = 0.f;
#pragma unroll
            for (int ks = 0; ks < 4; ks++) {
                uint32_t qh[4], qlo[4];
                *(uint4*)qh  = *(const uint4*)&smu[AQF + ((tile * 4 + ks) * 2 + 0) * 128 + l * 4];
                *(uint4*)qlo = *(const uint4*)&smu[AQF + ((tile * 4 + ks) * 2 + 1) * 128 + l * 4];
#pragma unroll
                for (int kb = 0; kb < 4; kb++) {
                    U64 kh, kl;
                    kh.u = lds_u64(&smu[KBUF(g, buf) + ((kb * 4 + ks) * 2 + 0) * 64 + l * 2]);
                    kl.u = lds_u64(&smu[KBUF(g, buf) + ((kb * 4 + ks) * 2 + 1) * 64 + l * 2]);
                    mma_bf16(sacc[kb], qh, kh.s);
                    mma_bf16(sacc[kb], qh, kl.s);
                    mma_bf16(sacc[kb], qlo, kh.s);
                }
            }

            // ---- mask + online softmax ----
            float mx0 = -INFINITY, mx1 = -INFINITY;
            const int colbase = t * 32 + qlc * 2;
#pragma unroll
            for (int kb = 0; kb < 4; kb++) {
                const int c0 = colbase + kb * 8;
                float s0 = sacc[kb][0] * 0.125f; if (c0 > r0 || s0 == 0.0f) s0 = -INFINITY;
                float s1 = sacc[kb][1] * 0.125f; if (c0 + 1 > r0 || s1 == 0.0f) s1 = -INFINITY;
                float s2 = sacc[kb][2] * 0.125f; if (c0 > r1 || s2 == 0.0f) s2 = -INFINITY;
                float s3 = sacc[kb][3] * 0.125f; if (c0 + 1 > r1 || s3 == 0.0f) s3 = -INFINITY;
                sacc[kb][0] = s0; sacc[kb][1] = s1; sacc[kb][2] = s2; sacc[kb][3] = s3;
                mx0 = fmaxf(mx0, fmaxf(s0, s1));
                mx1 = fmaxf(mx1, fmaxf(s2, s3));
            }
            mx0 = fmaxf(mx0, __shfl_xor_sync(0xffffffffu, mx0, 1));
            mx0 = fmaxf(mx0, __shfl_xor_sync(0xffffffffu, mx0, 2));
            mx1 = fmaxf(mx1, __shfl_xor_sync(0xffffffffu, mx1, 1));
            mx1 = fmaxf(mx1, __shfl_xor_sync(0xffffffffu, mx1, 2));

            const float mn0 = fmaxf(m0, mx0), mn1 = fmaxf(m1, mx1);
            const float f0 = __expf(m0 - mn0), f1 = __expf(m1 - mn1);
            m0 = mn0; m1 = mn1;

            float ps0 = 0.f, ps1 = 0.f;
#pragma unroll
            for (int kb = 0; kb < 4; kb++) {
                const float e0 = __expf(sacc[kb][0] - mn0);
                const float e1 = __expf(sacc[kb][1] - mn0);
                const float e2 = __expf(sacc[kb][2] - mn1);
                const float e3 = __expf(sacc[kb][3] - mn1);
                sacc[kb][0] = e0; sacc[kb][1] = e1; sacc[kb][2] = e2; sacc[kb][3] = e3;
                ps0 += e0 + e1; ps1 += e2 + e3;
            }
            ps0 += __shfl_xor_sync(0xffffffffu, ps0, 1);
            ps0 += __shfl_xor_sync(0xffffffffu, ps0, 2);
            ps1 += __shfl_xor_sync(0xffffffffu, ps1, 1);
            ps1 += __shfl_xor_sync(0xffffffffu, ps1, 2);
            ls0 = ls0 * f0 + ps0;
            ls1 = ls1 * f1 + ps1;

#pragma unroll
            for (int nt = 0; nt < 8; nt++) {
                oacc[nt][0] *= f0; oacc[nt][1] *= f0;
                oacc[nt][2] *= f1; oacc[nt][3] *= f1;
            }

            // ---- P @ V (2 kt of 16 keys) ----
#pragma unroll
            for (int kt = 0; kt < 2; kt++) {
                uint32_t ph[4], plo[4];
                split2(sacc[2 * kt][0],     sacc[2 * kt][1],     ph[0], plo[0]);
                split2(sacc[2 * kt][2],     sacc[2 * kt][3],     ph[1], plo[1]);
                split2(sacc[2 * kt + 1][0], sacc[2 * kt + 1][1], ph[2], plo[2]);
                split2(sacc[2 * kt + 1][2], sacc[2 * kt + 1][3], ph[3], plo[3]);
#pragma unroll
                for (int nt = 0; nt < 8; nt++) {
                    U64 vh, vl;
                    vh.u = lds_u64(&smu[VBUF(g, buf) + ((kt * 8 + nt) * 2 + 0) * 64 + l * 2]);
                    vl.u = lds_u64(&smu[VBUF(g, buf) + ((kt * 8 + nt) * 2 + 1) * 64 + l * 2]);
                    mma_bf16(oacc[nt], ph, vh.s);
                    mma_bf16(oacc[nt], ph, vl.s);
                    mma_bf16(oacc[nt], plo, vh.s);
                }
            }

            if (t + 4 < nkb) CP_WAIT(0);
            PBAR(g);             // both warps of this group done with buffers
        }

        // ---- 4-way split-KV merge ----
        __syncthreads();         // all compute done; smem buffers reusable
        float* stg = (float*)smu;
        if (g > 0) {
            float* sl = stg + (uint32_t)((g - 1) * 64 + tile * 32 + l) * 36;
#pragma unroll
            for (int nt = 0; nt < 8; nt++)
#pragma unroll
                for (int e = 0; e < 4; e++) sl[nt * 4 + e] = oacc[nt][e];
            sl[32] = m0; sl[33] = m1; sl[34] = ls0; sl[35] = ls1;
        }
        __syncthreads();
        if (g == 0) {
            float mm0 = m0, mm1 = m1;
#pragma unroll
            for (int gg = 1; gg < 4; gg++) {
                const float* sl = stg + (uint32_t)((gg - 1) * 64 + tile * 32 + l) * 36;
                mm0 = fmaxf(mm0, sl[32]);
                mm1 = fmaxf(mm1, sl[33]);
            }
            const float fA0 = __expf(m0 - mm0), fA1 = __expf(m1 - mm1);
            float den0 = ls0 * fA0, den1 = ls1 * fA1;
            float og[8][4];
#pragma unroll
            for (int nt = 0; nt < 8; nt++) {
                og[nt][0] = oacc[nt][0] * fA0;
                og[nt][1] = oacc[nt][1] * fA0;
                og[nt][2] = oacc[nt][2] * fA1;
                og[nt][3] = oacc[nt][3] * fA1;
            }
#pragma unroll
            for (int gg = 1; gg < 4; gg++) {
                const float* sl = stg + (uint32_t)((gg - 1) * 64 + tile * 32 + l) * 36;
                const float fB0 = __expf(sl[32] - mm0);
                const float fB1 = __expf(sl[33] - mm1);
                den0 += sl[34] * fB0;
                den1 += sl[35] * fB1;
#pragma unroll
                for (int nt = 0; nt < 8; nt++) {
                    og[nt][0] += sl[nt * 4 + 0] * fB0;
                    og[nt][1] += sl[nt * 4 + 1] * fB0;
                    og[nt][2] += sl[nt * 4 + 2] * fB1;
                    og[nt][3] += sl[nt * 4 + 3] * fB1;
                }
            }
            const float inv0 = 1.0f / den0, inv1 = 1.0f / den1;
#pragma unroll
            for (int nt = 0; nt < 8; nt++) {
                const int d0 = nt * 8 + qlc * 2;
                *(float2*)&ob[(size_t)r0 * HH + d0] =
                    make_float2(og[nt][0] * inv0, og[nt][1] * inv0);
                *(float2*)&ob[(size_t)r1 * HH + d0] =
                    make_float2(og[nt][2] * inv1, og[nt][3] * inv1);
            }
        }
    }
}

// ---------------------------------------------------------------------------
extern "C" void kernel_launch(void* const* d_in, const int* in_sizes, int n_in,
                              void* d_out, int out_size)
{
    const float* x  = (const float*)d_in[0];
    const float* Wq = (const float*)d_in[1];
    const float* Wk = (const float*)d_in[2];
    const float* Wv = (const float*)d_in[3];
    float* out = (float*)d_out;

    static int smem_set = 0;
    if (!smem_set) {
        cudaFuncSetAttribute(attn_kernel,
                             cudaFuncAttributeMaxDynamicSharedMemorySize,
                             ATTN_SMEM_BYTES);
        smem_set = 1;
    }

    split_a_kernel<<<4096, 256>>>(x);
    split_b_kernel<<<192, 256>>>(Wq, Wk, Wv);
    gemm_kernel<<<128, 256>>>();
    attn_kernel<<<dim3(32, BB), 256, ATTN_SMEM_BYTES>>>(out);
}

// round 16
// speedup vs baseline: 1.0788x; 1.0788x over previous
#include <cuda_runtime.h>
#include <cuda_bf16.h>
#include <math.h>
#include <stdint.h>

#define BB 4
#define TT 2048
#define CC 1024
#define HH 64
#define NROWS (BB * TT)   // 8192

// W fragments for proj GEMM
__device__ uint32_t g_bfrag[64 * 24 * 2 * 64];
// q/k/v in mma fragment form, produced by gemm epilogue
__device__ uint32_t g_qf[4 * 128 * 4 * 2 * 128];   // [b][mtile][ks][prec][lane*4+r]
__device__ uint32_t g_kf[4 * 256 * 4 * 2 * 64];    // [b][keyblk][ks][prec][lane*2+r]
__device__ uint32_t g_vf[4 * 128 * 8 * 2 * 64];    // [b][keytile][nt][prec][lane*2+r]

typedef unsigned long long ull;
union U64 { ull u; uint32_t s[2]; };

// ---------------- helpers ----------------
__device__ __forceinline__ ull lds_u64(const void* p) {
    uint32_t sa = (uint32_t)__cvta_generic_to_shared(p);
    ull r;
    asm volatile("ld.shared.u64 %0, [%1];" : "=l"(r) : "r"(sa));
    return r;
}
__device__ __forceinline__ void cp_async16(void* smem_dst, const void* gptr) {
    uint32_t sa = (uint32_t)__cvta_generic_to_shared(smem_dst);
    asm volatile("cp.async.cg.shared.global [%0], [%1], 16;" :: "r"(sa), "l"(gptr));
}
#define CP_COMMIT() asm volatile("cp.async.commit_group;")
#define CP_WAIT(n)  asm volatile("cp.async.wait_group %0;" :: "n"(n))
#define PBAR(g)     asm volatile("bar.sync %0, 64;" :: "r"((g) + 1) : "memory")

__device__ __forceinline__ uint32_t pack_bf16x2(float a, float b) {
    __nv_bfloat162 t;
    t.x = __float2bfloat16_rn(a);
    t.y = __float2bfloat16_rn(b);
    return *(uint32_t*)&t;
}
__device__ __forceinline__ void split2(float a, float b, uint32_t& hi, uint32_t& lo) {
    __nv_bfloat16 ha = __float2bfloat16_rn(a);
    __nv_bfloat16 hb = __float2bfloat16_rn(b);
    __nv_bfloat162 th; th.x = ha; th.y = hb;
    hi = *(uint32_t*)&th;
    lo = pack_bf16x2(a - __bfloat162float(ha), b - __bfloat162float(hb));
}
__device__ __forceinline__ void mma_bf16(float* c, const uint32_t* a, const uint32_t* b) {
    asm volatile(
        "mma.sync.aligned.m16n8k16.row.col.f32.bf16.bf16.f32 "
        "{%0,%1,%2,%3}, {%4,%5,%6,%7}, {%8,%9}, {%0,%1,%2,%3};"
        : "+f"(c[0]), "+f"(c[1]), "+f"(c[2]), "+f"(c[3])
        : "r"(a[0]), "r"(a[1]), "r"(a[2]), "r"(a[3]), "r"(b[0]), "r"(b[1]));
}

// ---------------------------------------------------------------------------
// Kernel 0: W -> bf16 (hi,lo) B-fragments.
// ---------------------------------------------------------------------------
__global__ __launch_bounds__(256) void split_b_kernel(
    const float* __restrict__ Wq,
    const float* __restrict__ Wk,
    const float* __restrict__ Wv)
{
    const int idx  = blockIdx.x * 256 + threadIdx.x;
    const int lane = idx & 31;
    const int nt   = (idx >> 5) % 24;
    const int ks   = idx / 768;
    const int n    = nt * 8 + (lane >> 2);
    const float* W = (n < 64) ? Wq : (n < 128) ? Wk : Wv;
    const int nc   = n & 63;
    const uint32_t base = (uint32_t)(ks * 24 + nt) * 128;

#pragma unroll
    for (int r = 0; r < 2; r++) {
        const int k = ks * 16 + ((lane & 3) << 1) + (r << 3);
        const float v0 = W[k * HH + nc];
        const float v1 = W[(k + 1) * HH + nc];
        uint32_t hi, lo;
        split2(v0, v1, hi, lo);
        g_bfrag[base + lane * 2 + r]      = hi;
        g_bfrag[base + 64 + lane * 2 + r] = lo;
    }
}

// ---------------------------------------------------------------------------
// Kernel 1: QKV projection via mma.sync, 256 threads / 8 warps.
// A path: direct f32 LDG from x (register double-buffer) + in-kernel split2
// -> no split_a kernel, no fragment round-trip. B via cp.async fragments.
// Warp = (mtile = w&3, nhalf = w>>2); 12 n-tiles x 3 mma per warp per k-step.
// Epilogue: nhalf0 -> Q + K(ks 0,1); nhalf1 -> K(ks 2,3) + V.
// ---------------------------------------------------------------------------
__global__ __launch_bounds__(256) void gemm_kernel(const float* __restrict__ x)
{
    __shared__ uint32_t Bs[2][24 * 128];   // 24 KB
    __shared__ float    Vsm[4][16][64];    // 16 KB

    const int tid   = threadIdx.x;
    const int w     = tid >> 5;
    const int lane  = tid & 31;
    const int mtile = w & 3;
    const int nhalf = w >> 2;
    const int ntb   = nhalf * 12;
    const int row0  = blockIdx.x * 64;
    const int qlr   = lane >> 2;
    const int qlc   = lane & 3;

    // lane's base into x: row = row0 + mtile*16 + qlr, col = qlc*2
    const float* xl = x + (size_t)(row0 + mtile * 16 + qlr) * CC + qlc * 2;

    float acc[12][4];
#pragma unroll
    for (int nt = 0; nt < 12; nt++)
#pragma unroll
        for (int e = 0; e < 4; e++) acc[nt][e] = 0.f;

    // prologue: A regs for ks=0, B fragments for ks=0 -> buf 0
    float2 arc[4];
#pragma unroll
    for (int r = 0; r < 4; r++)
        arc[r] = *(const float2*)&xl[((r & 1) * 8) * CC + ((r >> 1) * 8)];
    {
#pragma unroll
        for (int i = 0; i < 3; i++) {
            const int u = tid + i * 256;
            cp_async16(&Bs[0][u * 4], g_bfrag + u * 4);
        }
        CP_COMMIT();
    }

    for (int ks = 0; ks < 64; ks++) {
        const int buf = ks & 1;
        CP_WAIT(0);
        __syncthreads();

        if (ks + 1 < 64) {
#pragma unroll
            for (int i = 0; i < 3; i++) {
                const int u = tid + i * 256;
                cp_async16(&Bs[buf ^ 1][u * 4],
                           g_bfrag + (uint32_t)(ks + 1) * 3072 + u * 4);
            }
            CP_COMMIT();
        }

        // prefetch next A regs
        float2 arn[4];
        if (ks + 1 < 64) {
#pragma unroll
            for (int r = 0; r < 4; r++)
                arn[r] = *(const float2*)&xl[((r & 1) * 8) * CC + (ks + 1) * 16 + ((r >> 1) * 8)];
        }

        // split current A regs to bf16 hi/lo fragments
        uint32_t ah[4], al[4];
#pragma unroll
        for (int r = 0; r < 4; r++)
            split2(arc[r].x, arc[r].y, ah[r], al[r]);

#pragma unroll
        for (int nt = 0; nt < 12; nt++) {
            const int ntg = ntb + nt;
            uint32_t bh[2], bl[2];
            *(uint2*)bh = *(const uint2*)&Bs[buf][ntg * 128 + lane * 2];
            *(uint2*)bl = *(const uint2*)&Bs[buf][ntg * 128 + 64 + lane * 2];
            mma_bf16(acc[nt], ah, bh);
            mma_bf16(acc[nt], ah, bl);
            mma_bf16(acc[nt], al, bh);
        }

#pragma unroll
        for (int r = 0; r < 4; r++) arc[r] = arn[r];
    }

    // ---- epilogue: write fragment-form q/k/v ----
    const int rw  = row0 + mtile * 16;
    const int bb  = rw >> 11;
    const int mtb = (rw & 2047) >> 4;
    const int kb0 = (rw & 2047) >> 3;
    const int ktb = mtb;

    if (nhalf == 0) {
        // Q: A-fragments from acc[0..7]
#pragma unroll
        for (int ks = 0; ks < 4; ks++) {
            uint32_t h0, l0, h1, l1, h2, l2, h3, l3;
            split2(acc[2 * ks][0],     acc[2 * ks][1],     h0, l0);
            split2(acc[2 * ks][2],     acc[2 * ks][3],     h1, l1);
            split2(acc[2 * ks + 1][0], acc[2 * ks + 1][1], h2, l2);
            split2(acc[2 * ks + 1][2], acc[2 * ks + 1][3], h3, l3);
            const uint32_t base = (uint32_t)(((bb * 128 + mtb) * 4 + ks) * 2) * 128 + lane * 4;
            *(uint4*)&g_qf[base]       = make_uint4(h0, h1, h2, h3);
            *(uint4*)&g_qf[base + 128] = make_uint4(l0, l1, l2, l3);
        }
        // K: ks 0,1 from acc[8..11]
#pragma unroll
        for (int ks = 0; ks < 2; ks++) {
            const float* aE = acc[8 + 2 * ks];
            const float* aO = acc[9 + 2 * ks];
            uint32_t b0h, b0l, b1h, b1l;
            split2(aE[0], aE[1], b0h, b0l);
            split2(aO[0], aO[1], b1h, b1l);
            uint32_t base = (uint32_t)(((bb * 256 + kb0) * 4 + ks) * 2) * 64 + lane * 2;
            *(uint2*)&g_kf[base]      = make_uint2(b0h, b1h);
            *(uint2*)&g_kf[base + 64] = make_uint2(b0l, b1l);
            split2(aE[2], aE[3], b0h, b0l);
            split2(aO[2], aO[3], b1h, b1l);
            base = (uint32_t)(((bb * 256 + kb0 + 1) * 4 + ks) * 2) * 64 + lane * 2;
            *(uint2*)&g_kf[base]      = make_uint2(b0h, b1h);
            *(uint2*)&g_kf[base + 64] = make_uint2(b0l, b1l);
        }
    } else {
        // K: ks 2,3 from acc[0..3]
#pragma unroll
        for (int ks = 2; ks < 4; ks++) {
            const float* aE = acc[2 * ks - 4];
            const float* aO = acc[2 * ks - 3];
            uint32_t b0h, b0l, b1h, b1l;
            split2(aE[0], aE[1], b0h, b0l);
            split2(aO[0], aO[1], b1h, b1l);
            uint32_t base = (uint32_t)(((bb * 256 + kb0) * 4 + ks) * 2) * 64 + lane * 2;
            *(uint2*)&g_kf[base]      = make_uint2(b0h, b1h);
            *(uint2*)&g_kf[base + 64] = make_uint2(b0l, b1l);
            split2(aE[2], aE[3], b0h, b0l);
            split2(aO[2], aO[3], b1h, b1l);
            base = (uint32_t)(((bb * 256 + kb0 + 1) * 4 + ks) * 2) * 64 + lane * 2;
            *(uint2*)&g_kf[base]      = make_uint2(b0h, b1h);
            *(uint2*)&g_kf[base + 64] = make_uint2(b0l, b1l);
        }
        // V: stage f32 to smem, then transposed B-fragments (acc[4..11])
#pragma unroll
        for (int dt = 0; dt < 8; dt++) {
            const int d0 = dt * 8 + qlc * 2;
            Vsm[mtile][qlr][d0]         = acc[4 + dt][0];
            Vsm[mtile][qlr][d0 + 1]     = acc[4 + dt][1];
            Vsm[mtile][qlr + 8][d0]     = acc[4 + dt][2];
            Vsm[mtile][qlr + 8][d0 + 1] = acc[4 + dt][3];
        }
        __syncwarp();
#pragma unroll
        for (int nt = 0; nt < 8; nt++) {
#pragma unroll
            for (int r = 0; r < 2; r++) {
                const int kl_ = qlc * 2 + r * 8;
                const int dd  = nt * 8 + qlr;
                uint32_t h, lo;
                split2(Vsm[mtile][kl_][dd], Vsm[mtile][kl_ + 1][dd], h, lo);
                const uint32_t base = (uint32_t)(((bb * 128 + ktb) * 8 + nt) * 2) * 64 + lane * 2 + r;
                g_vf[base]      = h;
                g_vf[base + 64] = lo;
            }
        }
    }
}

// ---------------------------------------------------------------------------
// Kernel 2: causal attention, all-HMMA, 4-way key split across 8 warps.
// (unchanged from round 15: 32.0us measured)
// ---------------------------------------------------------------------------
#define KBUF(g, buf) (((g) * 2 + (buf)) * 2048)
#define VBUF(g, buf) (16384 + ((g) * 2 + (buf)) * 2048)
#define AQF 32768
#define ATTN_SMEM_BYTES (34816 * 4)    // 139264 B = 136 KB

__global__ __launch_bounds__(256) void attn_kernel(float* __restrict__ out)
{
    extern __shared__ uint32_t smu[];

    const int b    = blockIdx.y;
    const int p    = blockIdx.x;         // 0..31
    const int tid  = threadIdx.x;
    const int w    = tid >> 5;
    const int l    = tid & 31;
    const int tile = w & 1;              // m16 tile within the 32-row q-tile
    const int g    = w >> 1;             // key group (0..3)
    const int lt   = tid & 63;           // thread index within group
    const int qlr  = l >> 2;
    const int qlc  = l & 3;

    const uint32_t* qfb = g_qf + (size_t)b * 131072;
    const uint32_t* kfb = g_kf + (size_t)b * 131072;
    const uint32_t* vfb = g_vf + (size_t)b * 131072;
    float* ob = out + (size_t)b * TT * HH;

    for (int phase = 0; phase < 2; phase++) {
        const int qt = phase ? (63 - p) : p;
        const int qs = qt * 32;
        __syncthreads();    // previous phase fully done with smem (incl. merge)

        const int nkb = (qs + 63) >> 5;   // 32-key tiles = qt + 1

        // Q fragments (8 KB, all threads)
        {
            const uint32_t* src = qfb + (uint32_t)(qt * 2) * 1024;
#pragma unroll
            for (int i = 0; i < 2; i++) {
                const int u = tid + i * 256;
                cp_async16(&smu[AQF + u * 4], src + u * 4);
            }
        }
        // group's first key tile (t = g), if any
        if (g < nkb) {
            const uint32_t* ks_ = kfb + (uint32_t)g * 2048;
            const uint32_t* vs_ = vfb + (uint32_t)g * 2048;
#pragma unroll
            for (int i = 0; i < 8; i++) {
                const int u = lt + i * 64;
                cp_async16(&smu[KBUF(g, 0) + u * 4], ks_ + u * 4);
                cp_async16(&smu[VBUF(g, 0) + u * 4], vs_ + u * 4);
            }
        }
        CP_COMMIT();
        CP_WAIT(0);
        __syncthreads();

        float oacc[8][4];
#pragma unroll
        for (int nt = 0; nt < 8; nt++)
#pragma unroll
            for (int e = 0; e < 4; e++) oacc[nt][e] = 0.f;
        float m0 = -INFINITY, m1 = -INFINITY, ls0 = 0.f, ls1 = 0.f;
        const int r0 = qs + tile * 16 + qlr;
        const int r1 = r0 + 8;

        for (int t = g; t < nkb; t += 4) {
            const int buf = (t >> 2) & 1;
            if (t + 4 < nkb) {
                const uint32_t* ks_ = kfb + (uint32_t)(t + 4) * 2048;
                const uint32_t* vs_ = vfb + (uint32_t)(t + 4) * 2048;
#pragma unroll
                for (int i = 0; i < 8; i++) {
                    const int u = lt + i * 64;
                    cp_async16(&smu[KBUF(g, buf ^ 1) + u * 4], ks_ + u * 4);
                    cp_async16(&smu[VBUF(g, buf ^ 1) + u * 4], vs_ + u * 4);
                }
                CP_COMMIT();
            }

            // ---- scores: 3-product split bf16 HMMA (4 key blocks of 8) ----
            float sacc[4][4];
#pragma unroll
            for (int kb = 0; kb < 4; kb++)
#pragma unroll
                for (int e = 0; e < 4; e++) sacc[kb][e] = 0.f;
#pragma unroll
            for (int ks = 0; ks < 4; ks++) {
                uint32_t qh[4], qlo[4];
                *(uint4*)qh  = *(const uint4*)&smu[AQF + ((tile * 4 + ks) * 2 + 0) * 128 + l * 4];
                *(uint4*)qlo = *(const uint4*)&smu[AQF + ((tile * 4 + ks) * 2 + 1) * 128 + l * 4];
#pragma unroll
                for (int kb = 0; kb < 4; kb++) {
                    U64 kh, kl;
                    kh.u = lds_u64(&smu[KBUF(g, buf) + ((kb * 4 + ks) * 2 + 0) * 64 + l * 2]);
                    kl.u = lds_u64(&smu[KBUF(g, buf) + ((kb * 4 + ks) * 2 + 1) * 64 + l * 2]);
                    mma_bf16(sacc[kb], qh, kh.s);
                    mma_bf16(sacc[kb], qh, kl.s);
                    mma_bf16(sacc[kb], qlo, kh.s);
                }
            }

            // ---- mask + online softmax ----
            float mx0 = -INFINITY, mx1 = -INFINITY;
            const int colbase = t * 32 + qlc * 2;
#pragma unroll
            for (int kb = 0; kb < 4; kb++) {
                const int c0 = colbase + kb * 8;
                float s0 = sacc[kb][0] * 0.125f; if (c0 > r0 || s0 == 0.0f) s0 = -INFINITY;
                float s1 = sacc[kb][1] * 0.125f; if (c0 + 1 > r0 || s1 == 0.0f) s1 = -INFINITY;
                float s2 = sacc[kb][2] * 0.125f; if (c0 > r1 || s2 == 0.0f) s2 = -INFINITY;
                float s3 = sacc[kb][3] * 0.125f; if (c0 + 1 > r1 || s3 == 0.0f) s3 = -INFINITY;
                sacc[kb][0] = s0; sacc[kb][1] = s1; sacc[kb][2] = s2; sacc[kb][3] = s3;
                mx0 = fmaxf(mx0, fmaxf(s0, s1));
                mx1 = fmaxf(mx1, fmaxf(s2, s3));
            }
            mx0 = fmaxf(mx0, __shfl_xor_sync(0xffffffffu, mx0, 1));
            mx0 = fmaxf(mx0, __shfl_xor_sync(0xffffffffu, mx0, 2));
            mx1 = fmaxf(mx1, __shfl_xor_sync(0xffffffffu, mx1, 1));
            mx1 = fmaxf(mx1, __shfl_xor_sync(0xffffffffu, mx1, 2));

            const float mn0 = fmaxf(m0, mx0), mn1 = fmaxf(m1, mx1);
            const float f0 = __expf(m0 - mn0), f1 = __expf(m1 - mn1);
            m0 = mn0; m1 = mn1;

            float ps0 = 0.f, ps1 = 0.f;
#pragma unroll
            for (int kb = 0; kb < 4; kb++) {
                const float e0 = __expf(sacc[kb][0] - mn0);
                const float e1 = __expf(sacc[kb][1] - mn0);
                const float e2 = __expf(sacc[kb][2] - mn1);
                const float e3 = __expf(sacc[kb][3] - mn1);
                sacc[kb][0] = e0; sacc[kb][1] = e1; sacc[kb][2] = e2; sacc[kb][3] = e3;
                ps0 += e0 + e1; ps1 += e2 + e3;
            }
            ps0 += __shfl_xor_sync(0xffffffffu, ps0, 1);
            ps0 += __shfl_xor_sync(0xffffffffu, ps0, 2);
            ps1 += __shfl_xor_sync(0xffffffffu, ps1, 1);
            ps1 += __shfl_xor_sync(0xffffffffu, ps1, 2);
            ls0 = ls0 * f0 + ps0;
            ls1 = ls1 * f1 + ps1;

#pragma unroll
            for (int nt = 0; nt < 8; nt++) {
                oacc[nt][0] *= f0; oacc[nt][1] *= f0;
                oacc[nt][2] *= f1; oacc[nt][3] *= f1;
            }

            // ---- P @ V (2 kt of 16 keys) ----
#pragma unroll
            for (int kt = 0; kt < 2; kt++) {
                uint32_t ph[4], plo[4];
                split2(sacc[2 * kt][0],     sacc[2 * kt][1],     ph[0], plo[0]);
                split2(sacc[2 * kt][2],     sacc[2 * kt][3],     ph[1], plo[1]);
                split2(sacc[2 * kt + 1][0], sacc[2 * kt + 1][1], ph[2], plo[2]);
                split2(sacc[2 * kt + 1][2], sacc[2 * kt + 1][3], ph[3], plo[3]);
#pragma unroll
                for (int nt = 0; nt < 8; nt++) {
                    U64 vh, vl;
                    vh.u = lds_u64(&smu[VBUF(g, buf) + ((kt * 8 + nt) * 2 + 0) * 64 + l * 2]);
                    vl.u = lds_u64(&smu[VBUF(g, buf) + ((kt * 8 + nt) * 2 + 1) * 64 + l * 2]);
                    mma_bf16(oacc[nt], ph, vh.s);
                    mma_bf16(oacc[nt], ph, vl.s);
                    mma_bf16(oacc[nt], plo, vh.s);
                }
            }

            if (t + 4 < nkb) CP_WAIT(0);
            PBAR(g);             // both warps of this group done with buffers
        }

        // ---- 4-way split-KV merge ----
        __syncthreads();         // all compute done; smem buffers reusable
        float* stg = (float*)smu;
        if (g > 0) {
            float* sl = stg + (uint32_t)((g - 1) * 64 + tile * 32 + l) * 36;
#pragma unroll
            for (int nt = 0; nt < 8; nt++)
#pragma unroll
                for (int e = 0; e < 4; e++) sl[nt * 4 + e] = oacc[nt][e];
            sl[32] = m0; sl[33] = m1; sl[34] = ls0; sl[35] = ls1;
        }
        __syncthreads();
        if (g == 0) {
            float mm0 = m0, mm1 = m1;
#pragma unroll
            for (int gg = 1; gg < 4; gg++) {
                const float* sl = stg + (uint32_t)((gg - 1) * 64 + tile * 32 + l) * 36;
                mm0 = fmaxf(mm0, sl[32]);
                mm1 = fmaxf(mm1, sl[33]);
            }
            const float fA0 = __expf(m0 - mm0), fA1 = __expf(m1 - mm1);
            float den0 = ls0 * fA0, den1 = ls1 * fA1;
            float og[8][4];
#pragma unroll
            for (int nt = 0; nt < 8; nt++) {
                og[nt][0] = oacc[nt][0] * fA0;
                og[nt][1] = oacc[nt][1] * fA0;
                og[nt][2] = oacc[nt][2] * fA1;
                og[nt][3] = oacc[nt][3] * fA1;
            }
#pragma unroll
            for (int gg = 1; gg < 4; gg++) {
                const float* sl = stg + (uint32_t)((gg - 1) * 64 + tile * 32 + l) * 36;
                const float fB0 = __expf(sl[32] - mm0);
                const float fB1 = __expf(sl[33] - mm1);
                den0 += sl[34] * fB0;
                den1 += sl[35] * fB1;
#pragma unroll
                for (int nt = 0; nt < 8; nt++) {
                    og[nt][0] += sl[nt * 4 + 0] * fB0;
                    og[nt][1] += sl[nt * 4 + 1] * fB0;
                    og[nt][2] += sl[nt * 4 + 2] * fB1;
                    og[nt][3] += sl[nt * 4 + 3] * fB1;
                }
            }
            const float inv0 = 1.0f / den0, inv1 = 1.0f / den1;
#pragma unroll
            for (int nt = 0; nt < 8; nt++) {
                const int d0 = nt * 8 + qlc * 2;
                *(float2*)&ob[(size_t)r0 * HH + d0] =
                    make_float2(og[nt][0] * inv0, og[nt][1] * inv0);
                *(float2*)&ob[(size_t)r1 * HH + d0] =
                    make_float2(og[nt][2] * inv1, og[nt][3] * inv1);
            }
        }
    }
}

// ---------------------------------------------------------------------------
extern "C" void kernel_launch(void* const* d_in, const int* in_sizes, int n_in,
                              void* d_out, int out_size)
{
    const float* x  = (const float*)d_in[0];
    const float* Wq = (const float*)d_in[1];
    const float* Wk = (const float*)d_in[2];
    const float* Wv = (const float*)d_in[3];
    float* out = (float*)d_out;

    static int smem_set = 0;
    if (!smem_set) {
        cudaFuncSetAttribute(attn_kernel,
                             cudaFuncAttributeMaxDynamicSharedMemorySize,
                             ATTN_SMEM_BYTES);
        smem_set = 1;
    }

    split_b_kernel<<<192, 256>>>(Wq, Wk, Wv);
    gemm_kernel<<<128, 256>>>(x);
    attn_kernel<<<dim3(32, BB), 256, ATTN_SMEM_BYTES>>>(out);
}

// round 17
// speedup vs baseline: 1.1015x; 1.0211x over previous
#include <cuda_runtime.h>
#include <cuda_bf16.h>
#include <math.h>
#include <stdint.h>

#define BB 4
#define TT 2048
#define CC 1024
#define HH 64
#define NROWS (BB * TT)   // 8192

// W fragments for proj GEMM
__device__ uint32_t g_bfrag[64 * 24 * 2 * 64];
// q/k/v in mma fragment form, produced by gemm epilogue
__device__ uint32_t g_qf[4 * 128 * 4 * 2 * 128];   // [b][mtile][ks][prec][lane*4+r]
__device__ uint32_t g_kf[4 * 256 * 4 * 2 * 64];    // [b][keyblk][ks][prec][lane*2+r]
__device__ uint32_t g_vf[4 * 128 * 8 * 2 * 64];    // [b][keytile][nt][prec][lane*2+r]

typedef unsigned long long ull;
union U64 { ull u; uint32_t s[2]; };

// ---------------- helpers ----------------
__device__ __forceinline__ ull lds_u64(const void* p) {
    uint32_t sa = (uint32_t)__cvta_generic_to_shared(p);
    ull r;
    asm volatile("ld.shared.u64 %0, [%1];" : "=l"(r) : "r"(sa));
    return r;
}
__device__ __forceinline__ void cp_async16(void* smem_dst, const void* gptr) {
    uint32_t sa = (uint32_t)__cvta_generic_to_shared(smem_dst);
    asm volatile("cp.async.cg.shared.global [%0], [%1], 16;" :: "r"(sa), "l"(gptr));
}
#define CP_COMMIT() asm volatile("cp.async.commit_group;")
#define CP_WAIT(n)  asm volatile("cp.async.wait_group %0;" :: "n"(n))
#define PBAR(g)     asm volatile("bar.sync %0, 64;" :: "r"((g) + 1) : "memory")

__device__ __forceinline__ uint32_t pack_bf16x2(float a, float b) {
    __nv_bfloat162 t;
    t.x = __float2bfloat16_rn(a);
    t.y = __float2bfloat16_rn(b);
    return *(uint32_t*)&t;
}
__device__ __forceinline__ void split2(float a, float b, uint32_t& hi, uint32_t& lo) {
    __nv_bfloat16 ha = __float2bfloat16_rn(a);
    __nv_bfloat16 hb = __float2bfloat16_rn(b);
    __nv_bfloat162 th; th.x = ha; th.y = hb;
    hi = *(uint32_t*)&th;
    lo = pack_bf16x2(a - __bfloat162float(ha), b - __bfloat162float(hb));
}
__device__ __forceinline__ void mma_bf16(float* c, const uint32_t* a, const uint32_t* b) {
    asm volatile(
        "mma.sync.aligned.m16n8k16.row.col.f32.bf16.bf16.f32 "
        "{%0,%1,%2,%3}, {%4,%5,%6,%7}, {%8,%9}, {%0,%1,%2,%3};"
        : "+f"(c[0]), "+f"(c[1]), "+f"(c[2]), "+f"(c[3])
        : "r"(a[0]), "r"(a[1]), "r"(a[2]), "r"(a[3]), "r"(b[0]), "r"(b[1]));
}

// ---------------------------------------------------------------------------
// Kernel 0: W -> bf16 (hi,lo) B-fragments.
// ---------------------------------------------------------------------------
__global__ __launch_bounds__(256) void split_b_kernel(
    const float* __restrict__ Wq,
    const float* __restrict__ Wk,
    const float* __restrict__ Wv)
{
    const int idx  = blockIdx.x * 256 + threadIdx.x;
    const int lane = idx & 31;
    const int nt   = (idx >> 5) % 24;
    const int ks   = idx / 768;
    const int n    = nt * 8 + (lane >> 2);
    const float* W = (n < 64) ? Wq : (n < 128) ? Wk : Wv;
    const int nc   = n & 63;
    const uint32_t base = (uint32_t)(ks * 24 + nt) * 128;

#pragma unroll
    for (int r = 0; r < 2; r++) {
        const int k = ks * 16 + ((lane & 3) << 1) + (r << 3);
        const float v0 = W[k * HH + nc];
        const float v1 = W[(k + 1) * HH + nc];
        uint32_t hi, lo;
        split2(v0, v1, hi, lo);
        g_bfrag[base + lane * 2 + r]      = hi;
        g_bfrag[base + 64 + lane * 2 + r] = lo;
    }
}

// ---------------------------------------------------------------------------
// Kernel 1: QKV projection via mma.sync, 256 threads / 8 warps.
// mma issued product-major in halves of 6 n-tiles -> dependent mma on the
// same accumulator are >=6 apart (was back-to-back -> latency stalls).
// ---------------------------------------------------------------------------
__global__ __launch_bounds__(256) void gemm_kernel(const float* __restrict__ x)
{
    __shared__ uint32_t Bs[2][24 * 128];   // 24 KB
    __shared__ float    Vsm[4][16][64];    // 16 KB

    const int tid   = threadIdx.x;
    const int w     = tid >> 5;
    const int lane  = tid & 31;
    const int mtile = w & 3;
    const int nhalf = w >> 2;
    const int ntb   = nhalf * 12;
    const int row0  = blockIdx.x * 64;
    const int qlr   = lane >> 2;
    const int qlc   = lane & 3;

    const float* xl = x + (size_t)(row0 + mtile * 16 + qlr) * CC + qlc * 2;

    float acc[12][4];
#pragma unroll
    for (int nt = 0; nt < 12; nt++)
#pragma unroll
        for (int e = 0; e < 4; e++) acc[nt][e] = 0.f;

    float2 arc[4];
#pragma unroll
    for (int r = 0; r < 4; r++)
        arc[r] = *(const float2*)&xl[((r & 1) * 8) * CC + ((r >> 1) * 8)];
    {
#pragma unroll
        for (int i = 0; i < 3; i++) {
            const int u = tid + i * 256;
            cp_async16(&Bs[0][u * 4], g_bfrag + u * 4);
        }
        CP_COMMIT();
    }

    for (int ks = 0; ks < 64; ks++) {
        const int buf = ks & 1;
        CP_WAIT(0);
        __syncthreads();

        if (ks + 1 < 64) {
#pragma unroll
            for (int i = 0; i < 3; i++) {
                const int u = tid + i * 256;
                cp_async16(&Bs[buf ^ 1][u * 4],
                           g_bfrag + (uint32_t)(ks + 1) * 3072 + u * 4);
            }
            CP_COMMIT();
        }

        float2 arn[4];
        if (ks + 1 < 64) {
#pragma unroll
            for (int r = 0; r < 4; r++)
                arn[r] = *(const float2*)&xl[((r & 1) * 8) * CC + (ks + 1) * 16 + ((r >> 1) * 8)];
        }

        uint32_t ah[4], al[4];
#pragma unroll
        for (int r = 0; r < 4; r++)
            split2(arc[r].x, arc[r].y, ah[r], al[r]);

#pragma unroll
        for (int half = 0; half < 2; half++) {
            uint2 bhv[6], blv[6];
#pragma unroll
            for (int nt = 0; nt < 6; nt++) {
                const int ntg = ntb + half * 6 + nt;
                bhv[nt] = *(const uint2*)&Bs[buf][ntg * 128 + lane * 2];
                blv[nt] = *(const uint2*)&Bs[buf][ntg * 128 + 64 + lane * 2];
            }
            // product-major: dependent mma on acc[i] are 6 apart
#pragma unroll
            for (int nt = 0; nt < 6; nt++)
                mma_bf16(acc[half * 6 + nt], ah, (const uint32_t*)&bhv[nt]);
#pragma unroll
            for (int nt = 0; nt < 6; nt++)
                mma_bf16(acc[half * 6 + nt], ah, (const uint32_t*)&blv[nt]);
#pragma unroll
            for (int nt = 0; nt < 6; nt++)
                mma_bf16(acc[half * 6 + nt], al, (const uint32_t*)&bhv[nt]);
        }

#pragma unroll
        for (int r = 0; r < 4; r++) arc[r] = arn[r];
    }

    // ---- epilogue: write fragment-form q/k/v ----
    const int rw  = row0 + mtile * 16;
    const int bb  = rw >> 11;
    const int mtb = (rw & 2047) >> 4;
    const int kb0 = (rw & 2047) >> 3;
    const int ktb = mtb;

    if (nhalf == 0) {
#pragma unroll
        for (int ks = 0; ks < 4; ks++) {
            uint32_t h0, l0, h1, l1, h2, l2, h3, l3;
            split2(acc[2 * ks][0],     acc[2 * ks][1],     h0, l0);
            split2(acc[2 * ks][2],     acc[2 * ks][3],     h1, l1);
            split2(acc[2 * ks + 1][0], acc[2 * ks + 1][1], h2, l2);
            split2(acc[2 * ks + 1][2], acc[2 * ks + 1][3], h3, l3);
            const uint32_t base = (uint32_t)(((bb * 128 + mtb) * 4 + ks) * 2) * 128 + lane * 4;
            *(uint4*)&g_qf[base]       = make_uint4(h0, h1, h2, h3);
            *(uint4*)&g_qf[base + 128] = make_uint4(l0, l1, l2, l3);
        }
#pragma unroll
        for (int ks = 0; ks < 2; ks++) {
            const float* aE = acc[8 + 2 * ks];
            const float* aO = acc[9 + 2 * ks];
            uint32_t b0h, b0l, b1h, b1l;
            split2(aE[0], aE[1], b0h, b0l);
            split2(aO[0], aO[1], b1h, b1l);
            uint32_t base = (uint32_t)(((bb * 256 + kb0) * 4 + ks) * 2) * 64 + lane * 2;
            *(uint2*)&g_kf[base]      = make_uint2(b0h, b1h);
            *(uint2*)&g_kf[base + 64] = make_uint2(b0l, b1l);
            split2(aE[2], aE[3], b0h, b0l);
            split2(aO[2], aO[3], b1h, b1l);
            base = (uint32_t)(((bb * 256 + kb0 + 1) * 4 + ks) * 2) * 64 + lane * 2;
            *(uint2*)&g_kf[base]      = make_uint2(b0h, b1h);
            *(uint2*)&g_kf[base + 64] = make_uint2(b0l, b1l);
        }
    } else {
#pragma unroll
        for (int ks = 2; ks < 4; ks++) {
            const float* aE = acc[2 * ks - 4];
            const float* aO = acc[2 * ks - 3];
            uint32_t b0h, b0l, b1h, b1l;
            split2(aE[0], aE[1], b0h, b0l);
            split2(aO[0], aO[1], b1h, b1l);
            uint32_t base = (uint32_t)(((bb * 256 + kb0) * 4 + ks) * 2) * 64 + lane * 2;
            *(uint2*)&g_kf[base]      = make_uint2(b0h, b1h);
            *(uint2*)&g_kf[base + 64] = make_uint2(b0l, b1l);
            split2(aE[2], aE[3], b0h, b0l);
            split2(aO[2], aO[3], b1h, b1l);
            base = (uint32_t)(((bb * 256 + kb0 + 1) * 4 + ks) * 2) * 64 + lane * 2;
            *(uint2*)&g_kf[base]      = make_uint2(b0h, b1h);
            *(uint2*)&g_kf[base + 64] = make_uint2(b0l, b1l);
        }
#pragma unroll
        for (int dt = 0; dt < 8; dt++) {
            const int d0 = dt * 8 + qlc * 2;
            Vsm[mtile][qlr][d0]         = acc[4 + dt][0];
            Vsm[mtile][qlr][d0 + 1]     = acc[4 + dt][1];
            Vsm[mtile][qlr + 8][d0]     = acc[4 + dt][2];
            Vsm[mtile][qlr + 8][d0 + 1] = acc[4 + dt][3];
        }
        __syncwarp();
#pragma unroll
        for (int nt = 0; nt < 8; nt++) {
#pragma unroll
            for (int r = 0; r < 2; r++) {
                const int kl_ = qlc * 2 + r * 8;
                const int dd  = nt * 8 + qlr;
                uint32_t h, lo;
                split2(Vsm[mtile][kl_][dd], Vsm[mtile][kl_ + 1][dd], h, lo);
                const uint32_t base = (uint32_t)(((bb * 128 + ktb) * 8 + nt) * 2) * 64 + lane * 2 + r;
                g_vf[base]      = h;
                g_vf[base + 64] = lo;
            }
        }
    }
}

// ---------------------------------------------------------------------------
// Kernel 2: causal attention, all-HMMA, 4-way key split across 8 warps.
// Scores use dual accumulator sets (even/odd k-step) + product-major issue;
// PV preloads all 8 V fragments + product-major issue. Dependent mma on the
// same accumulator are >=8 apart.
// ---------------------------------------------------------------------------
#define KBUF(g, buf) (((g) * 2 + (buf)) * 2048)
#define VBUF(g, buf) (16384 + ((g) * 2 + (buf)) * 2048)
#define AQF 32768
#define ATTN_SMEM_BYTES (34816 * 4)    // 139264 B = 136 KB

__global__ __launch_bounds__(256) void attn_kernel(float* __restrict__ out)
{
    extern __shared__ uint32_t smu[];

    const int b    = blockIdx.y;
    const int p    = blockIdx.x;         // 0..31
    const int tid  = threadIdx.x;
    const int w    = tid >> 5;
    const int l    = tid & 31;
    const int tile = w & 1;
    const int g    = w >> 1;             // key group (0..3)
    const int lt   = tid & 63;
    const int qlr  = l >> 2;
    const int qlc  = l & 3;

    const uint32_t* qfb = g_qf + (size_t)b * 131072;
    const uint32_t* kfb = g_kf + (size_t)b * 131072;
    const uint32_t* vfb = g_vf + (size_t)b * 131072;
    float* ob = out + (size_t)b * TT * HH;

    for (int phase = 0; phase < 2; phase++) {
        const int qt = phase ? (63 - p) : p;
        const int qs = qt * 32;
        __syncthreads();

        const int nkb = (qs + 63) >> 5;   // 32-key tiles = qt + 1

        {
            const uint32_t* src = qfb + (uint32_t)(qt * 2) * 1024;
#pragma unroll
            for (int i = 0; i < 2; i++) {
                const int u = tid + i * 256;
                cp_async16(&smu[AQF + u * 4], src + u * 4);
            }
        }
        if (g < nkb) {
            const uint32_t* ks_ = kfb + (uint32_t)g * 2048;
            const uint32_t* vs_ = vfb + (uint32_t)g * 2048;
#pragma unroll
            for (int i = 0; i < 8; i++) {
                const int u = lt + i * 64;
                cp_async16(&smu[KBUF(g, 0) + u * 4], ks_ + u * 4);
                cp_async16(&smu[VBUF(g, 0) + u * 4], vs_ + u * 4);
            }
        }
        CP_COMMIT();
        CP_WAIT(0);
        __syncthreads();

        float oacc[8][4];
#pragma unroll
        for (int nt = 0; nt < 8; nt++)
#pragma unroll
            for (int e = 0; e < 4; e++) oacc[nt][e] = 0.f;
        float m0 = -INFINITY, m1 = -INFINITY, ls0 = 0.f, ls1 = 0.f;
        const int r0 = qs + tile * 16 + qlr;
        const int r1 = r0 + 8;

        for (int t = g; t < nkb; t += 4) {
            const int buf = (t >> 2) & 1;
            if (t + 4 < nkb) {
                const uint32_t* ks_ = kfb + (uint32_t)(t + 4) * 2048;
                const uint32_t* vs_ = vfb + (uint32_t)(t + 4) * 2048;
#pragma unroll
                for (int i = 0; i < 8; i++) {
                    const int u = lt + i * 64;
                    cp_async16(&smu[KBUF(g, buf ^ 1) + u * 4], ks_ + u * 4);
                    cp_async16(&smu[VBUF(g, buf ^ 1) + u * 4], vs_ + u * 4);
                }
                CP_COMMIT();
            }

            // ---- scores: dual accumulators + product-major (8 chains) ----
            float sacc[4][4], sacc2[4][4];
#pragma unroll
            for (int kb = 0; kb < 4; kb++)
#pragma unroll
                for (int e = 0; e < 4; e++) { sacc[kb][e] = 0.f; sacc2[kb][e] = 0.f; }

#pragma unroll
            for (int ks2 = 0; ks2 < 2; ks2++) {
                const int ksA = 2 * ks2, ksB = 2 * ks2 + 1;
                uint32_t qhA[4], qloA[4], qhB[4], qloB[4];
                *(uint4*)qhA  = *(const uint4*)&smu[AQF + ((tile * 4 + ksA) * 2 + 0) * 128 + l * 4];
                *(uint4*)qloA = *(const uint4*)&smu[AQF + ((tile * 4 + ksA) * 2 + 1) * 128 + l * 4];
                *(uint4*)qhB  = *(const uint4*)&smu[AQF + ((tile * 4 + ksB) * 2 + 0) * 128 + l * 4];
                *(uint4*)qloB = *(const uint4*)&smu[AQF + ((tile * 4 + ksB) * 2 + 1) * 128 + l * 4];
                U64 khA[4], klA[4], khB[4], klB[4];
#pragma unroll
                for (int kb = 0; kb < 4; kb++) {
                    khA[kb].u = lds_u64(&smu[KBUF(g, buf) + ((kb * 4 + ksA) * 2 + 0) * 64 + l * 2]);
                    klA[kb].u = lds_u64(&smu[KBUF(g, buf) + ((kb * 4 + ksA) * 2 + 1) * 64 + l * 2]);
                    khB[kb].u = lds_u64(&smu[KBUF(g, buf) + ((kb * 4 + ksB) * 2 + 0) * 64 + l * 2]);
                    klB[kb].u = lds_u64(&smu[KBUF(g, buf) + ((kb * 4 + ksB) * 2 + 1) * 64 + l * 2]);
                }
#pragma unroll
                for (int kb = 0; kb < 4; kb++) mma_bf16(sacc[kb],  qhA,  khA[kb].s);
#pragma unroll
                for (int kb = 0; kb < 4; kb++) mma_bf16(sacc2[kb], qhB,  khB[kb].s);
#pragma unroll
                for (int kb = 0; kb < 4; kb++) mma_bf16(sacc[kb],  qhA,  klA[kb].s);
#pragma unroll
                for (int kb = 0; kb < 4; kb++) mma_bf16(sacc2[kb], qhB,  klB[kb].s);
#pragma unroll
                for (int kb = 0; kb < 4; kb++) mma_bf16(sacc[kb],  qloA, khA[kb].s);
#pragma unroll
                for (int kb = 0; kb < 4; kb++) mma_bf16(sacc2[kb], qloB, khB[kb].s);
            }
#pragma unroll
            for (int kb = 0; kb < 4; kb++)
#pragma unroll
                for (int e = 0; e < 4; e++) sacc[kb][e] += sacc2[kb][e];

            // ---- mask + online softmax ----
            float mx0 = -INFINITY, mx1 = -INFINITY;
            const int colbase = t * 32 + qlc * 2;
#pragma unroll
            for (int kb = 0; kb < 4; kb++) {
                const int c0 = colbase + kb * 8;
                float s0 = sacc[kb][0] * 0.125f; if (c0 > r0 || s0 == 0.0f) s0 = -INFINITY;
                float s1 = sacc[kb][1] * 0.125f; if (c0 + 1 > r0 || s1 == 0.0f) s1 = -INFINITY;
                float s2 = sacc[kb][2] * 0.125f; if (c0 > r1 || s2 == 0.0f) s2 = -INFINITY;
                float s3 = sacc[kb][3] * 0.125f; if (c0 + 1 > r1 || s3 == 0.0f) s3 = -INFINITY;
                sacc[kb][0] = s0; sacc[kb][1] = s1; sacc[kb][2] = s2; sacc[kb][3] = s3;
                mx0 = fmaxf(mx0, fmaxf(s0, s1));
                mx1 = fmaxf(mx1, fmaxf(s2, s3));
            }
            mx0 = fmaxf(mx0, __shfl_xor_sync(0xffffffffu, mx0, 1));
            mx0 = fmaxf(mx0, __shfl_xor_sync(0xffffffffu, mx0, 2));
            mx1 = fmaxf(mx1, __shfl_xor_sync(0xffffffffu, mx1, 1));
            mx1 = fmaxf(mx1, __shfl_xor_sync(0xffffffffu, mx1, 2));

            const float mn0 = fmaxf(m0, mx0), mn1 = fmaxf(m1, mx1);
            const float f0 = __expf(m0 - mn0), f1 = __expf(m1 - mn1);
            m0 = mn0; m1 = mn1;

            float ps0 = 0.f, ps1 = 0.f;
#pragma unroll
            for (int kb = 0; kb < 4; kb++) {
                const float e0 = __expf(sacc[kb][0] - mn0);
                const float e1 = __expf(sacc[kb][1] - mn0);
                const float e2 = __expf(sacc[kb][2] - mn1);
                const float e3 = __expf(sacc[kb][3] - mn1);
                sacc[kb][0] = e0; sacc[kb][1] = e1; sacc[kb][2] = e2; sacc[kb][3] = e3;
                ps0 += e0 + e1; ps1 += e2 + e3;
            }
            ps0 += __shfl_xor_sync(0xffffffffu, ps0, 1);
            ps0 += __shfl_xor_sync(0xffffffffu, ps0, 2);
            ps1 += __shfl_xor_sync(0xffffffffu, ps1, 1);
            ps1 += __shfl_xor_sync(0xffffffffu, ps1, 2);
            ls0 = ls0 * f0 + ps0;
            ls1 = ls1 * f1 + ps1;

#pragma unroll
            for (int nt = 0; nt < 8; nt++) {
                oacc[nt][0] *= f0; oacc[nt][1] *= f0;
                oacc[nt][2] *= f1; oacc[nt][3] *= f1;
            }

            // ---- P @ V : preload V frags, product-major (8 chains) ----
#pragma unroll
            for (int kt = 0; kt < 2; kt++) {
                uint32_t ph[4], plo[4];
                split2(sacc[2 * kt][0],     sacc[2 * kt][1],     ph[0], plo[0]);
                split2(sacc[2 * kt][2],     sacc[2 * kt][3],     ph[1], plo[1]);
                split2(sacc[2 * kt + 1][0], sacc[2 * kt + 1][1], ph[2], plo[2]);
                split2(sacc[2 * kt + 1][2], sacc[2 * kt + 1][3], ph[3], plo[3]);
                U64 vh[8], vl[8];
#pragma unroll
                for (int nt = 0; nt < 8; nt++) {
                    vh[nt].u = lds_u64(&smu[VBUF(g, buf) + ((kt * 8 + nt) * 2 + 0) * 64 + l * 2]);
                    vl[nt].u = lds_u64(&smu[VBUF(g, buf) + ((kt * 8 + nt) * 2 + 1) * 64 + l * 2]);
                }
#pragma unroll
                for (int nt = 0; nt < 8; nt++) mma_bf16(oacc[nt], ph,  vh[nt].s);
#pragma unroll
                for (int nt = 0; nt < 8; nt++) mma_bf16(oacc[nt], ph,  vl[nt].s);
#pragma unroll
                for (int nt = 0; nt < 8; nt++) mma_bf16(oacc[nt], plo, vh[nt].s);
            }

            if (t + 4 < nkb) CP_WAIT(0);
            PBAR(g);
        }

        // ---- 4-way split-KV merge ----
        __syncthreads();
        float* stg = (float*)smu;
        if (g > 0) {
            float* sl = stg + (uint32_t)((g - 1) * 64 + tile * 32 + l) * 36;
#pragma unroll
            for (int nt = 0; nt < 8; nt++)
#pragma unroll
                for (int e = 0; e < 4; e++) sl[nt * 4 + e] = oacc[nt][e];
            sl[32] = m0; sl[33] = m1; sl[34] = ls0; sl[35] = ls1;
        }
        __syncthreads();
        if (g == 0) {
            float mm0 = m0, mm1 = m1;
#pragma unroll
            for (int gg = 1; gg < 4; gg++) {
                const float* sl = stg + (uint32_t)((gg - 1) * 64 + tile * 32 + l) * 36;
                mm0 = fmaxf(mm0, sl[32]);
                mm1 = fmaxf(mm1, sl[33]);
            }
            const float fA0 = __expf(m0 - mm0), fA1 = __expf(m1 - mm1);
            float den0 = ls0 * fA0, den1 = ls1 * fA1;
            float og[8][4];
#pragma unroll
            for (int nt = 0; nt < 8; nt++) {
                og[nt][0] = oacc[nt][0] * fA0;
                og[nt][1] = oacc[nt][1] * fA0;
                og[nt][2] = oacc[nt][2] * fA1;
                og[nt][3] = oacc[nt][3] * fA1;
            }
#pragma unroll
            for (int gg = 1; gg < 4; gg++) {
                const float* sl = stg + (uint32_t)((gg - 1) * 64 + tile * 32 + l) * 36;
                const float fB0 = __expf(sl[32] - mm0);
                const float fB1 = __expf(sl[33] - mm1);
                den0 += sl[34] * fB0;
                den1 += sl[35] * fB1;
#pragma unroll
                for (int nt = 0; nt < 8; nt++) {
                    og[nt][0] += sl[nt * 4 + 0] * fB0;
                    og[nt][1] += sl[nt * 4 + 1] * fB0;
                    og[nt][2] += sl[nt * 4 + 2] * fB1;
                    og[nt][3] += sl[nt * 4 + 3] * fB1;
                }
            }
            const float inv0 = 1.0f / den0, inv1 = 1.0f / den1;
#pragma unroll
            for (int nt = 0; nt < 8; nt++) {
                const int d0 = nt * 8 + qlc * 2;
                *(float2*)&ob[(size_t)r0 * HH + d0] =
                    make_float2(og[nt][0] * inv0, og[nt][1] * inv0);
                *(float2*)&ob[(size_t)r1 * HH + d0] =
                    make_float2(og[nt][2] * inv1, og[nt][3] * inv1);
            }
        }
    }
}

// ---------------------------------------------------------------------------
extern "C" void kernel_launch(void* const* d_in, const int* in_sizes, int n_in,
                              void* d_out, int out_size)
{
    const float* x  = (const float*)d_in[0];
    const float* Wq = (const float*)d_in[1];
    const float* Wk = (const float*)d_in[2];
    const float* Wv = (const float*)d_in[3];
    float* out = (float*)d_out;

    static int smem_set = 0;
    if (!smem_set) {
        cudaFuncSetAttribute(attn_kernel,
                             cudaFuncAttributeMaxDynamicSharedMemorySize,
                             ATTN_SMEM_BYTES);
        smem_set = 1;
    }

    split_b_kernel<<<192, 256>>>(Wq, Wk, Wv);
    gemm_kernel<<<128, 256>>>(x);
    attn_kernel<<<dim3(32, BB), 256, ATTN_SMEM_BYTES>>>(out);
}